// round 4
// baseline (speedup 1.0000x reference)
#include <cuda_runtime.h>
#include <cstdint>

// Problem constants
#define T_TOK 4096      // B*S
#define HDIM  1024
#define HFF   4096
#define NEXP  8
#define KTOP  2

// GEMM tiling
#define BM 128
#define BN 128
#define BKT 16
#define NTHREADS 256

// ---------------- device scratch (static: no allocations allowed) ----------
__device__ int   g_cnt[NEXP];
__device__ int   g_base[NEXP];
__device__ int   g_list[NEXP * T_TOK];
__device__ float g_gval[NEXP * T_TOK];
__device__ int   g_i32flag;
// H buffer: one row per (expert, slot) entry; padded by BM rows so tail tiles
// of the LAST expert can be read (never written) without OOB.
__device__ float g_hbuf[(size_t)(T_TOK * KTOP + BM) * HFF];

// ---------------- helpers --------------------------------------------------
__device__ __forceinline__ float tf32r(float x) {
    uint32_t o;
    asm("cvt.rna.tf32.f32 %0, %1;" : "=r"(o) : "f"(x));
    return __uint_as_float(o);
}

__device__ __forceinline__ float gelu_tanh(float x) {
    // jax.nn.gelu default: approximate=True (tanh form)
    float x3 = x * x * x;
    float t = tanhf(0.7978845608028654f * (x + 0.044715f * x3));
    return 0.5f * x * (1.0f + t);
}

#define MMA_TF32(c, a, b)                                                   \
    asm volatile(                                                           \
        "mma.sync.aligned.m16n8k8.row.col.f32.tf32.tf32.f32 "               \
        "{%0,%1,%2,%3}, {%4,%5,%6,%7}, {%8,%9}, {%0,%1,%2,%3};"             \
        : "+f"((c)[0]), "+f"((c)[1]), "+f"((c)[2]), "+f"((c)[3])            \
        : "r"((a)[0]), "r"((a)[1]), "r"((a)[2]), "r"((a)[3]),               \
          "r"((b)[0]), "r"((b)[1]))

// ---------------- small kernels --------------------------------------------
__global__ void k_zero(float4* out4, int n4) {
    int i = blockIdx.x * blockDim.x + threadIdx.x;
    if (i < n4) out4[i] = make_float4(0.f, 0.f, 0.f, 0.f);
    if (i < NEXP) g_cnt[i] = 0;
    if (i == 0) g_i32flag = 0;
}

// topk_indices may be int64 (x64 on) or int32 (default jax). Values are 0..7,
// so with int64 every odd int32 word is 0. Scan only the first T*K int32
// words (in-bounds for BOTH dtypes): any nonzero odd word => int32 data.
__global__ void k_detect(const int* __restrict__ idx32) {
    int i = blockIdx.x * blockDim.x + threadIdx.x;
    int v = 0;
    for (int j = i; j < (T_TOK * KTOP) / 2; j += gridDim.x * blockDim.x)
        v |= idx32[2 * j + 1];
    if (v) atomicOr(&g_i32flag, 1);
}

__global__ void k_gate(const void* __restrict__ idx_raw,
                       const float* __restrict__ probs) {
    int t = blockIdx.x * blockDim.x + threadIdx.x;
    if (t >= T_TOK) return;
    int e0, e1;
    if (g_i32flag) {
        const int* p = (const int*)idx_raw;
        e0 = p[2 * t]; e1 = p[2 * t + 1];
    } else {
        const long long* p = (const long long*)idx_raw;
        e0 = (int)p[2 * t]; e1 = (int)p[2 * t + 1];
    }
    float p0 = probs[2 * t], p1 = probs[2 * t + 1];
    if (e0 == e1) { p0 = fmaxf(p0, p1); e1 = -1; }  // max over k dedups
    if ((unsigned)e0 < NEXP) {
        int pos = atomicAdd(&g_cnt[e0], 1);
        g_list[e0 * T_TOK + pos] = t;
        g_gval[e0 * T_TOK + pos] = p0;
    }
    if ((unsigned)e1 < NEXP) {
        int pos = atomicAdd(&g_cnt[e1], 1);
        g_list[e1 * T_TOK + pos] = t;
        g_gval[e1 * T_TOK + pos] = p1;
    }
}

__global__ void k_prefix() {
    int s = 0;
    for (int e = 0; e < NEXP; ++e) { g_base[e] = s; s += g_cnt[e]; }
}

// ---------------- GEMM mainloop shared pieces (macros for two kernels) -----
// Smem layout: [stage][k][row+pad]  — fragment loads are bank-conflict-free.

#define GEMM_PROLOG()                                                        \
    const int tid = threadIdx.x;                                             \
    const int lane = tid & 31, warp = tid >> 5;                              \
    const int wm = warp & 1, wn = warp >> 1;                                 \
    const int g = lane >> 2, tq = lane & 3;                                  \
    float acc[4][4][4];                                                      \
    _Pragma("unroll") for (int mi = 0; mi < 4; ++mi)                         \
    _Pragma("unroll") for (int ni = 0; ni < 4; ++ni)                         \
    _Pragma("unroll") for (int ci = 0; ci < 4; ++ci) acc[mi][ni][ci] = 0.f;

#define STS_STAGE(s)                                                         \
    do {                                                                     \
        _Pragma("unroll") for (int i = 0; i < 2; ++i) {                      \
            As[s][ac[i] + 0][ar[i]] = tf32r(fa[i].x);                        \
            As[s][ac[i] + 1][ar[i]] = tf32r(fa[i].y);                        \
            As[s][ac[i] + 2][ar[i]] = tf32r(fa[i].z);                        \
            As[s][ac[i] + 3][ar[i]] = tf32r(fa[i].w);                        \
            Bs[s][ac[i] + 0][ar[i]] = tf32r(fb[i].x);                        \
            Bs[s][ac[i] + 1][ar[i]] = tf32r(fb[i].y);                        \
            Bs[s][ac[i] + 2][ar[i]] = tf32r(fb[i].z);                        \
            Bs[s][ac[i] + 3][ar[i]] = tf32r(fb[i].w);                        \
        }                                                                    \
    } while (0)

#define COMPUTE_STAGE(cur)                                                   \
    do {                                                                     \
        _Pragma("unroll") for (int ks = 0; ks < 2; ++ks) {                   \
            const int kb = ks * 8;                                           \
            uint32_t aF[4][4], bF[4][2];                                     \
            _Pragma("unroll") for (int mi = 0; mi < 4; ++mi) {               \
                int rb = wm * 64 + mi * 16;                                  \
                aF[mi][0] = __float_as_uint(As[cur][kb + tq][rb + g]);       \
                aF[mi][1] = __float_as_uint(As[cur][kb + tq][rb + g + 8]);   \
                aF[mi][2] = __float_as_uint(As[cur][kb + tq + 4][rb + g]);   \
                aF[mi][3] = __float_as_uint(As[cur][kb + tq + 4][rb + g + 8]);\
            }                                                                \
            _Pragma("unroll") for (int ni = 0; ni < 4; ++ni) {               \
                int nb = wn * 32 + ni * 8;                                   \
                bF[ni][0] = __float_as_uint(Bs[cur][kb + tq][nb + g]);       \
                bF[ni][1] = __float_as_uint(Bs[cur][kb + tq + 4][nb + g]);   \
            }                                                                \
            _Pragma("unroll") for (int mi = 0; mi < 4; ++mi)                 \
            _Pragma("unroll") for (int ni = 0; ni < 4; ++ni)                 \
                MMA_TF32(acc[mi][ni], aF[mi], bF[ni]);                       \
        }                                                                    \
    } while (0)

#define GEMM_MAINLOOP(KDIM)                                                  \
    do {                                                                     \
        _Pragma("unroll") for (int i = 0; i < 2; ++i) {                      \
            fa[i] = *(const float4*)(Arow[i]);                               \
            fb[i] = *(const float4*)(Brow[i]);                               \
        }                                                                    \
        STS_STAGE(0);                                                        \
        __syncthreads();                                                     \
        const int KT = (KDIM) / BKT;                                         \
        for (int kt = 0; kt < KT; ++kt) {                                    \
            const int cur = kt & 1;                                          \
            if (kt + 1 < KT) {                                               \
                const int k0 = (kt + 1) * BKT;                               \
                _Pragma("unroll") for (int i = 0; i < 2; ++i) {              \
                    fa[i] = *(const float4*)(Arow[i] + k0);                  \
                    fb[i] = *(const float4*)(Brow[i] + k0);                  \
                }                                                            \
            }                                                                \
            COMPUTE_STAGE(cur);                                              \
            if (kt + 1 < KT) {                                               \
                STS_STAGE(cur ^ 1);                                          \
                __syncthreads();                                             \
            }                                                                \
        }                                                                    \
    } while (0)

// ---------------- GEMM1: H = gelu(X_gathered @ W1[e]^T) --------------------
__global__ __launch_bounds__(NTHREADS, 2)
void k_gemm1(const float* __restrict__ x, const float* __restrict__ W1) {
    __shared__ float As[2][BKT][BM + 4];
    __shared__ float Bs[2][BKT][BN + 4];

    const int e = blockIdx.z;
    const int cnt = g_cnt[e];
    const int m0 = blockIdx.x * BM;
    if (m0 >= cnt) return;
    const int n0 = blockIdx.y * BN;

    GEMM_PROLOG();

    const float* Arow[2];
    const float* Brow[2];
    int ar[2], ac[2];
#pragma unroll
    for (int i = 0; i < 2; ++i) {
        int idx = tid + i * 256;
        int r = idx >> 2, c = (idx & 3) << 2;
        ar[i] = r; ac[i] = c;
        int m = m0 + r;
        int tok = (m < cnt) ? g_list[e * T_TOK + m] : 0;
        Arow[i] = x + (size_t)tok * HDIM + c;
        Brow[i] = W1 + (size_t)e * HFF * HDIM + (size_t)(n0 + r) * HDIM + c;
    }

    float4 fa[2], fb[2];
    GEMM_MAINLOOP(HDIM);

    // Epilogue: gelu + store H rows (guard: never write rows >= cnt — those
    // slots belong to the next expert's region).
    const int base = g_base[e];
#pragma unroll
    for (int mi = 0; mi < 4; ++mi) {
        const int rb = wm * 64 + mi * 16;
        const int mA = m0 + rb + g;
        const int mB = mA + 8;
#pragma unroll
        for (int ni = 0; ni < 4; ++ni) {
            const int col = n0 + wn * 32 + ni * 8 + 2 * tq;
            if (mA < cnt) {
                float2 v;
                v.x = gelu_tanh(acc[mi][ni][0]);
                v.y = gelu_tanh(acc[mi][ni][1]);
                *(float2*)&g_hbuf[(size_t)(base + mA) * HFF + col] = v;
            }
            if (mB < cnt) {
                float2 v;
                v.x = gelu_tanh(acc[mi][ni][2]);
                v.y = gelu_tanh(acc[mi][ni][3]);
                *(float2*)&g_hbuf[(size_t)(base + mB) * HFF + col] = v;
            }
        }
    }
}

// ---------------- GEMM2: out[tok] += gate * (H @ W2[e]^T) -------------------
__global__ __launch_bounds__(NTHREADS, 2)
void k_gemm2(const float* __restrict__ W2, float* __restrict__ out) {
    __shared__ float As[2][BKT][BM + 4];
    __shared__ float Bs[2][BKT][BN + 4];

    const int e = blockIdx.z;
    const int cnt = g_cnt[e];
    const int m0 = blockIdx.x * BM;
    if (m0 >= cnt) return;
    const int n0 = blockIdx.y * BN;
    const int base = g_base[e];

    GEMM_PROLOG();

    const float* Arow[2];
    const float* Brow[2];
    int ar[2], ac[2];
#pragma unroll
    for (int i = 0; i < 2; ++i) {
        int idx = tid + i * 256;
        int r = idx >> 2, c = (idx & 3) << 2;
        ar[i] = r; ac[i] = c;
        // rows >= cnt read garbage inside the padded buffer (results discarded)
        Arow[i] = g_hbuf + (size_t)(base + m0 + r) * HFF + c;
        Brow[i] = W2 + (size_t)e * HDIM * HFF + (size_t)(n0 + r) * HFF + c;
    }

    float4 fa[2], fb[2];
    GEMM_MAINLOOP(HFF);

    // Epilogue: gated accumulate into out (token may appear for 2 experts).
#pragma unroll
    for (int mi = 0; mi < 4; ++mi) {
        const int rb = wm * 64 + mi * 16;
        const int mA = m0 + rb + g;
        const int mB = mA + 8;
        int tokA = 0, tokB = 0;
        float gA = 0.f, gB = 0.f;
        if (mA < cnt) { tokA = g_list[e * T_TOK + mA]; gA = g_gval[e * T_TOK + mA]; }
        if (mB < cnt) { tokB = g_list[e * T_TOK + mB]; gB = g_gval[e * T_TOK + mB]; }
#pragma unroll
        for (int ni = 0; ni < 4; ++ni) {
            const int col = n0 + wn * 32 + ni * 8 + 2 * tq;
            if (mA < cnt) {
                atomicAdd(&out[(size_t)tokA * HDIM + col],     gA * acc[mi][ni][0]);
                atomicAdd(&out[(size_t)tokA * HDIM + col + 1], gA * acc[mi][ni][1]);
            }
            if (mB < cnt) {
                atomicAdd(&out[(size_t)tokB * HDIM + col],     gB * acc[mi][ni][2]);
                atomicAdd(&out[(size_t)tokB * HDIM + col + 1], gB * acc[mi][ni][3]);
            }
        }
    }
}

// ---------------- launch ----------------------------------------------------
extern "C" void kernel_launch(void* const* d_in, const int* in_sizes, int n_in,
                              void* d_out, int out_size) {
    const float* x     = (const float*)d_in[0];
    const float* probs = (const float*)d_in[1];
    const void*  idx   = d_in[2];
    const float* W1    = (const float*)d_in[3];
    const float* W2    = (const float*)d_in[4];
    float* out = (float*)d_out;

    const int n4 = out_size / 4;  // out_size = 4M float elements
    k_zero<<<(n4 + 255) / 256, 256>>>((float4*)out, n4);
    k_detect<<<32, 256>>>((const int*)idx);
    k_gate<<<(T_TOK + 255) / 256, 256>>>(idx, probs);
    k_prefix<<<1, 1>>>();

    dim3 g1(T_TOK / BM, HFF / BN, NEXP);   // (32, 32, 8); tail CTAs self-prune
    k_gemm1<<<g1, NTHREADS>>>(x, W1);

    dim3 g2(T_TOK / BM, HDIM / BN, NEXP);  // (32, 8, 8)
    k_gemm2<<<g2, NTHREADS>>>(W2, out);
}